// round 2
// baseline (speedup 1.0000x reference)
#include <cuda_runtime.h>
#include <cuda_bf16.h>
#include <math_constants.h>
#include <cstdint>

// Problem constants (fixed by the dataset)
#define NN   50000
#define EE   600000
#define GG   1000
#define HID  128
#define INF_ 64
#define EPS  1e-5f
#define SLOPE 0.01f

// ---------------------------------------------------------------------------
// Scratch (static __device__ arrays; no allocation anywhere)
// ---------------------------------------------------------------------------
__device__ float g_hs [NN * HID];    // gemm output * cs  (scatter source)
__device__ float g_agg[NN * HID];    // scatter target (self-cleared by colstats)
__device__ float g_y  [NN * HID];    // y = agg*cd (pre-norm layer output)
__device__ float g_cs [NN];
__device__ float g_cd [NN];
__device__ int   g_deg[2 * NN];
__device__ float g_stats[3 * 2 * HID];  // per-layer col sum / sumsq
__device__ float g_ab   [3 * 2 * HID];  // per-layer alpha / beta
__device__ int   g_gstart[GG + 1];

__device__ __forceinline__ float leaky(float v) { return v > 0.f ? v : SLOPE * v; }

__device__ __forceinline__ uint32_t to_tf32(float x) {
    uint32_t r;
    asm("cvt.rna.tf32.f32 %0, %1;" : "=r"(r) : "f"(x));
    return r;
}

// ---------------------------------------------------------------------------
// One consolidated setup zero: agg + deg + stats
// ---------------------------------------------------------------------------
__global__ void k_setup_zero(float4* __restrict__ agg4, int* __restrict__ deg,
                             float* __restrict__ stats) {
    int i = blockIdx.x * blockDim.x + threadIdx.x;
    int stride = gridDim.x * blockDim.x;
    for (int j = i; j < NN * HID / 4; j += stride)
        agg4[j] = make_float4(0.f, 0.f, 0.f, 0.f);
    for (int j = i; j < 2 * NN; j += stride) deg[j] = 0;
    for (int j = i; j < 3 * 2 * HID; j += stride) stats[j] = 0.f;
}

// ---------------------------------------------------------------------------
// Degrees / inverse sqrt degrees
// ---------------------------------------------------------------------------
__global__ void k_degrees(const int* __restrict__ src, const int* __restrict__ dst,
                          int* __restrict__ deg) {
    int e = blockIdx.x * blockDim.x + threadIdx.x;
    if (e >= EE) return;
    atomicAdd(&deg[src[e]], 1);
    atomicAdd(&deg[NN + dst[e]], 1);
}

__global__ void k_invdeg(const int* __restrict__ deg,
                         float* __restrict__ cs, float* __restrict__ cd) {
    int i = blockIdx.x * blockDim.x + threadIdx.x;
    if (i >= NN) return;
    cs[i] = rsqrtf(fmaxf((float)deg[i], 1.f));
    cd[i] = rsqrtf(fmaxf((float)deg[NN + i], 1.f));
}

// ---------------------------------------------------------------------------
// Graph segment starts (graph_ids sorted ascending)
// ---------------------------------------------------------------------------
__global__ void k_gstart(const int* __restrict__ gid, int* __restrict__ gstart) {
    int i = blockIdx.x * blockDim.x + threadIdx.x;
    if (i >= NN) return;
    int g  = gid[i];
    int gp = (i == 0) ? -1 : gid[i - 1];
    for (int gg = gp + 1; gg <= g; gg++) gstart[gg] = i;
    if (i == NN - 1)
        for (int gg = g + 1; gg <= GG; gg++) gstart[gg] = NN;
}

// ---------------------------------------------------------------------------
// TF32 tensor-core GEMM: out[N,128] = f(X)[N,K] @ W[K,128], scaled by cs[row].
// If NORM: f(x) = leaky(x*alpha[c] + beta[c]) applied during smem staging
// (this fuses the previous layer's GraphNorm+leaky into the load).
// Block: 128 rows x 128 cols, 8 warps. Warp = 16-row strip x 128 cols
// = 16 mma tiles m16n8k8. Inputs staged in smem pre-converted to tf32.
// ---------------------------------------------------------------------------
template <int K, bool NORM>
__global__ void __launch_bounds__(256, 2)
k_gemm_tf32(const float* __restrict__ X, const float* __restrict__ W,
            const float* __restrict__ cs, const float* __restrict__ ab,
            float* __restrict__ out) {
    __shared__ uint32_t Xs[128][36];   // +pad: conflict-free frag loads
    __shared__ uint32_t Ws[32][132];

    int tid  = threadIdx.x;
    int warp = tid >> 5, lane = tid & 31;
    int gid  = lane >> 2, tig = lane & 3;
    int row0 = blockIdx.x * 128;
    int wrow = warp * 16;

    float acc[16][4];
#pragma unroll
    for (int n = 0; n < 16; n++)
#pragma unroll
        for (int j = 0; j < 4; j++) acc[n][j] = 0.f;

    for (int k0 = 0; k0 < K; k0 += 32) {
        // stage W chunk [32][128] -> tf32
        for (int i = tid; i < 32 * 32; i += 256) {
            int r = i >> 5, c4 = (i & 31) * 4;
            float4 v = *(const float4*)&W[(k0 + r) * HID + c4];
            uint4 u = make_uint4(to_tf32(v.x), to_tf32(v.y), to_tf32(v.z), to_tf32(v.w));
            *(uint4*)&Ws[r][c4] = u;
        }
        // stage X chunk [128][32] -> (optional norm+leaky) -> tf32
        for (int i = tid; i < 128 * 8; i += 256) {
            int r = i >> 3, c4 = (i & 7) * 4;
            int g = row0 + r;
            float4 v = make_float4(0.f, 0.f, 0.f, 0.f);
            if (g < NN) v = *(const float4*)&X[(size_t)g * K + k0 + c4];
            if (NORM) {
                float4 a = __ldg((const float4*)ab + (k0 + c4) / 4);
                float4 b = __ldg((const float4*)(ab + HID) + (k0 + c4) / 4);
                v.x = leaky(v.x * a.x + b.x);
                v.y = leaky(v.y * a.y + b.y);
                v.z = leaky(v.z * a.z + b.z);
                v.w = leaky(v.w * a.w + b.w);
            }
            uint4 u = make_uint4(to_tf32(v.x), to_tf32(v.y), to_tf32(v.z), to_tf32(v.w));
            *(uint4*)&Xs[r][c4] = u;
        }
        __syncthreads();

#pragma unroll
        for (int k8 = 0; k8 < 32; k8 += 8) {
            uint32_t a0 = Xs[wrow + gid    ][k8 + tig];
            uint32_t a1 = Xs[wrow + gid + 8][k8 + tig];
            uint32_t a2 = Xs[wrow + gid    ][k8 + tig + 4];
            uint32_t a3 = Xs[wrow + gid + 8][k8 + tig + 4];
#pragma unroll
            for (int n = 0; n < 16; n++) {
                uint32_t b0 = Ws[k8 + tig    ][n * 8 + gid];
                uint32_t b1 = Ws[k8 + tig + 4][n * 8 + gid];
                asm volatile(
                    "mma.sync.aligned.m16n8k8.row.col.f32.tf32.tf32.f32 "
                    "{%0,%1,%2,%3}, {%4,%5,%6,%7}, {%8,%9}, {%0,%1,%2,%3};"
                    : "+f"(acc[n][0]), "+f"(acc[n][1]), "+f"(acc[n][2]), "+f"(acc[n][3])
                    : "r"(a0), "r"(a1), "r"(a2), "r"(a3), "r"(b0), "r"(b1));
            }
        }
        __syncthreads();
    }

    // epilogue: *cs[row], float2 stores
    int r1 = row0 + wrow + gid;
    int r2 = r1 + 8;
    float c1 = (r1 < NN) ? __ldg(&cs[r1]) : 0.f;
    float c2 = (r2 < NN) ? __ldg(&cs[r2]) : 0.f;
#pragma unroll
    for (int n = 0; n < 16; n++) {
        int col = n * 8 + 2 * tig;
        if (r1 < NN)
            *(float2*)&out[(size_t)r1 * HID + col] =
                make_float2(acc[n][0] * c1, acc[n][1] * c1);
        if (r2 < NN)
            *(float2*)&out[(size_t)r2 * HID + col] =
                make_float2(acc[n][2] * c2, acc[n][3] * c2);
    }
}

// ---------------------------------------------------------------------------
// Edge scatter: warp per edge, vector reduction add (v4.f32), L2-resident
// ---------------------------------------------------------------------------
__global__ void k_scatter(const float* __restrict__ hs,
                          const int* __restrict__ src, const int* __restrict__ dst,
                          float* __restrict__ agg) {
    int w = (blockIdx.x * blockDim.x + threadIdx.x) >> 5;
    if (w >= EE) return;
    int lane = threadIdx.x & 31;
    int s = __ldg(&src[w]);
    int d = __ldg(&dst[w]);
    float4 v = __ldg((const float4*)(hs + (size_t)s * HID) + lane);
    float* q = agg + (size_t)d * HID + lane * 4;
    asm volatile("red.global.add.v4.f32 [%0], {%1, %2, %3, %4};"
                 :: "l"(q), "f"(v.x), "f"(v.y), "f"(v.z), "f"(v.w)
                 : "memory");
}

// ---------------------------------------------------------------------------
// y = agg * cd  (into separate buffer), zero agg behind itself,
// accumulate column sum & sumsq into this layer's stats slot.
// ---------------------------------------------------------------------------
__global__ void k_colstats(float* __restrict__ agg, const float* __restrict__ cd,
                           float* __restrict__ y, float* __restrict__ stats) {
    const int ROWS = 256;
    int c = threadIdx.x & 127;
    int half = threadIdx.x >> 7;
    int base = blockIdx.x * ROWS;
    int end = min(base + ROWS, NN);
    float s = 0.f, s2 = 0.f;
    for (int r = base + half; r < end; r += 2) {
        size_t idx = (size_t)r * HID + c;
        float v = agg[idx] * __ldg(&cd[r]);
        agg[idx] = 0.f;               // self-clear for next layer
        y[idx] = v;
        s += v;
        s2 += v * v;
    }
    atomicAdd(&stats[c], s);
    atomicAdd(&stats[HID + c], s2);
}

// ---------------------------------------------------------------------------
// Per-channel alpha/beta from stats:
//  norm(y) = y*alpha + beta,  var = E[y^2] - m^2 (2s - s^2)
// ---------------------------------------------------------------------------
__global__ void k_alpha_beta(const float* __restrict__ stats,
                             const float* __restrict__ gw, const float* __restrict__ gb,
                             const float* __restrict__ gs, float* __restrict__ ab) {
    int c = threadIdx.x;
    float m   = stats[c] * (1.f / (float)NN);
    float ex2 = stats[HID + c] * (1.f / (float)NN);
    float s   = gs[c];
    float var = ex2 - m * m * (2.f * s - s * s);
    float inv = rsqrtf(var + EPS);
    float a   = inv * gw[c];
    ab[c]       = a;
    ab[HID + c] = gb[c] - s * m * a;
}

// ---------------------------------------------------------------------------
// Readout: block per graph, thread per channel, norm+leaky applied on the fly
// ---------------------------------------------------------------------------
__global__ void k_readout(const float* __restrict__ y, const float* __restrict__ ab,
                          const int* __restrict__ gstart,
                          float* __restrict__ out, int layer) {
    int g = blockIdx.x;
    int c = threadIdx.x;
    int s0 = gstart[g], s1 = gstart[g + 1];
    float a = __ldg(&ab[c]);
    float b = __ldg(&ab[HID + c]);
    float sum = 0.f, mx = -CUDART_INF_F, mn = CUDART_INF_F;
    for (int r = s0; r < s1; r++) {
        float v = leaky(__ldg(&y[(size_t)r * HID + c]) * a + b);
        sum += v;
        mx = fmaxf(mx, v);
        mn = fminf(mn, v);
    }
    int cnt = s1 - s0;
    float mean = sum / fmaxf((float)cnt, 1.f);
    if (cnt == 0) { mx = 0.f; mn = 0.f; }
    float* o = out + (size_t)g * (9 * HID) + layer * (3 * HID);
    o[c]           = leaky(mean);
    o[HID + c]     = leaky(mx);
    o[2 * HID + c] = leaky(mn);
}

// ---------------------------------------------------------------------------
// Launch
// ---------------------------------------------------------------------------
extern "C" void kernel_launch(void* const* d_in, const int* in_sizes, int n_in,
                              void* d_out, int out_size) {
    const float* X   = (const float*)d_in[0];
    const float* W1  = (const float*)d_in[1];
    const float* W2  = (const float*)d_in[2];
    const float* W3  = (const float*)d_in[3];
    const float* gw  = (const float*)d_in[4];
    const float* gb  = (const float*)d_in[5];
    const float* gs  = (const float*)d_in[6];
    const int*   src = (const int*)d_in[7];
    const int*   dst = (const int*)d_in[8];
    const int*   gid = (const int*)d_in[9];
    float* out = (float*)d_out;

    float *hs, *agg, *y, *cs, *cd, *stats, *ab;
    int *deg, *gstart;
    cudaGetSymbolAddress((void**)&hs,     g_hs);
    cudaGetSymbolAddress((void**)&agg,    g_agg);
    cudaGetSymbolAddress((void**)&y,      g_y);
    cudaGetSymbolAddress((void**)&cs,     g_cs);
    cudaGetSymbolAddress((void**)&cd,     g_cd);
    cudaGetSymbolAddress((void**)&stats,  g_stats);
    cudaGetSymbolAddress((void**)&ab,     g_ab);
    cudaGetSymbolAddress((void**)&deg,    g_deg);
    cudaGetSymbolAddress((void**)&gstart, g_gstart);

    // --- setup ---
    k_setup_zero<<<6250, 256>>>((float4*)agg, deg, stats);
    k_degrees<<<(EE + 255) / 256, 256>>>(src, dst, deg);
    k_invdeg<<<(NN + 255) / 256, 256>>>(deg, cs, cd);
    k_gstart<<<(NN + 255) / 256, 256>>>(gid, gstart);

    const float* Wl[3] = {W1, W2, W3};
    const int gemm_grid = (NN + 127) / 128;

    for (int L = 0; L < 3; L++) {
        // 1) hs = (f(x) @ W) * cs   (f = identity for L=0, norm+leaky of prev layer else)
        if (L == 0)
            k_gemm_tf32<INF_, false><<<gemm_grid, 256>>>(X, Wl[0], cs, nullptr, hs);
        else
            k_gemm_tf32<HID, true><<<gemm_grid, 256>>>(y, Wl[L], cs,
                                                       ab + (L - 1) * 2 * HID, hs);

        // 2) scatter-add over edges (agg pre-zeroed by setup / previous colstats)
        k_scatter<<<(EE * 32 + 255) / 256, 256>>>(hs, src, dst, agg);

        // 3) y = agg*cd, clear agg, column stats for this layer
        k_colstats<<<(NN + 255) / 256, 256>>>(agg, cd, y, stats + L * 2 * HID);

        // 4) per-channel alpha/beta
        k_alpha_beta<<<1, HID>>>(stats + L * 2 * HID, gw + L * HID, gb + L * HID,
                                 gs + L * HID, ab + L * 2 * HID);

        // 5) per-graph readout with norm+leaky on the fly
        k_readout<<<GG, HID>>>(y, ab + L * 2 * HID, gstart, out, L);
    }
}

// round 3
// speedup vs baseline: 2.1696x; 2.1696x over previous
#include <cuda_runtime.h>
#include <cuda_bf16.h>
#include <math_constants.h>
#include <cstdint>

// Problem constants (fixed by the dataset)
#define NN   50000
#define EE   600000
#define GG   1000
#define HID  128
#define INF_ 64
#define EPS  1e-5f
#define SLOPE 0.01f

#define NB_SCAN ((NN + 255) / 256)   // 196 scan blocks

// ---------------------------------------------------------------------------
// Scratch (static __device__ arrays; no allocation anywhere)
// ---------------------------------------------------------------------------
__device__ float g_hs [NN * HID];     // (x@W)*cs, gather source
__device__ float g_y  [NN * HID];     // y = sum_in * cd (pre-norm layer output)
__device__ float g_cs [NN];
__device__ float g_cd [NN];
__device__ int   g_deg[2 * NN];       // [0,N): outdeg(src), [N,2N): indeg(dst)
__device__ int   g_csr_start[NN + 1];
__device__ int   g_cursor[NN];
__device__ int   g_csr_src[EE];       // src node per in-edge, grouped by dst
__device__ int   g_bsum[256];
__device__ float g_stats[3 * 2 * HID];
__device__ float g_ab   [3 * 2 * HID];
__device__ int   g_gstart[GG + 1];

__device__ __forceinline__ float leaky(float v) { return v > 0.f ? v : SLOPE * v; }

// ---------------------------------------------------------------------------
// Setup zero: deg + stats
// ---------------------------------------------------------------------------
__global__ void k_setup_zero(int* __restrict__ deg, float* __restrict__ stats) {
    int i = blockIdx.x * blockDim.x + threadIdx.x;
    int stride = gridDim.x * blockDim.x;
    for (int j = i; j < 2 * NN; j += stride) deg[j] = 0;
    for (int j = i; j < 3 * 2 * HID; j += stride) stats[j] = 0.f;
}

// ---------------------------------------------------------------------------
// Degrees
// ---------------------------------------------------------------------------
__global__ void k_degrees(const int* __restrict__ src, const int* __restrict__ dst,
                          int* __restrict__ deg) {
    int e = blockIdx.x * blockDim.x + threadIdx.x;
    if (e >= EE) return;
    atomicAdd(&deg[src[e]], 1);
    atomicAdd(&deg[NN + dst[e]], 1);
}

__global__ void k_invdeg(const int* __restrict__ deg,
                         float* __restrict__ cs, float* __restrict__ cd) {
    int i = blockIdx.x * blockDim.x + threadIdx.x;
    if (i >= NN) return;
    cs[i] = rsqrtf(fmaxf((float)deg[i], 1.f));
    cd[i] = rsqrtf(fmaxf((float)deg[NN + i], 1.f));
}

// ---------------------------------------------------------------------------
// Graph segment starts (graph_ids sorted ascending)
// ---------------------------------------------------------------------------
__global__ void k_gstart(const int* __restrict__ gid, int* __restrict__ gstart) {
    int i = blockIdx.x * blockDim.x + threadIdx.x;
    if (i >= NN) return;
    int g  = gid[i];
    int gp = (i == 0) ? -1 : gid[i - 1];
    for (int gg = gp + 1; gg <= g; gg++) gstart[gg] = i;
    if (i == NN - 1)
        for (int gg = g + 1; gg <= GG; gg++) gstart[gg] = NN;
}

// ---------------------------------------------------------------------------
// CSR-by-dst: 3-step exclusive scan of in-degrees, then edge fill
// ---------------------------------------------------------------------------
__global__ void k_scan1(const int* __restrict__ indeg, int* __restrict__ bsum) {
    __shared__ int sh[256];
    int i = blockIdx.x * 256 + threadIdx.x;
    sh[threadIdx.x] = (i < NN) ? indeg[i] : 0;
    __syncthreads();
    for (int o = 128; o > 0; o >>= 1) {
        if (threadIdx.x < o) sh[threadIdx.x] += sh[threadIdx.x + o];
        __syncthreads();
    }
    if (threadIdx.x == 0) bsum[blockIdx.x] = sh[0];
}

__global__ void k_scan2(int* __restrict__ bsum) {   // 1 block, 256 threads
    __shared__ int sh[256];
    int tid = threadIdx.x;
    int v = (tid < NB_SCAN) ? bsum[tid] : 0;
    sh[tid] = v;
    __syncthreads();
    for (int o = 1; o < 256; o <<= 1) {
        int t = (tid >= o) ? sh[tid - o] : 0;
        __syncthreads();
        sh[tid] += t;
        __syncthreads();
    }
    if (tid < NB_SCAN) bsum[tid] = sh[tid] - v;     // exclusive
}

__global__ void k_scan3(const int* __restrict__ indeg, const int* __restrict__ bsum,
                        int* __restrict__ csr_start, int* __restrict__ cursor) {
    __shared__ int sh[256];
    int tid = threadIdx.x;
    int i = blockIdx.x * 256 + tid;
    int v = (i < NN) ? indeg[i] : 0;
    sh[tid] = v;
    __syncthreads();
    for (int o = 1; o < 256; o <<= 1) {
        int t = (tid >= o) ? sh[tid - o] : 0;
        __syncthreads();
        sh[tid] += t;
        __syncthreads();
    }
    int excl = sh[tid] - v + bsum[blockIdx.x];
    if (i < NN) { csr_start[i] = excl; cursor[i] = excl; }
    if (i == NN - 1) csr_start[NN] = excl + v;
}

__global__ void k_fill_csr(const int* __restrict__ src, const int* __restrict__ dst,
                           int* __restrict__ cursor, int* __restrict__ csr_src) {
    int e = blockIdx.x * blockDim.x + threadIdx.x;
    if (e >= EE) return;
    int pos = atomicAdd(&cursor[dst[e]], 1);
    csr_src[pos] = src[e];
}

// ---------------------------------------------------------------------------
// FFMA GEMM (proven): out[N,128] = f(X)[N,K] @ W[K,128], scaled by cs[row].
// If NORM: f(x) = leaky(x*alpha[c]+beta[c]) applied during Xs staging.
// Block: 64 rows x 128 cols, 256 threads, 8x4 micro-tile, BK=32.
// ---------------------------------------------------------------------------
template <int K, bool NORM>
__global__ void __launch_bounds__(256, 2)
k_gemm_cs(const float* __restrict__ X, const float* __restrict__ W,
          const float* __restrict__ cs, const float* __restrict__ ab,
          float* __restrict__ out) {
    constexpr int BK = 32;
    __shared__ float Ws[BK][HID];
    __shared__ float Xs[64][BK];

    int tid = threadIdx.x;
    int tx = tid & 31, ty = tid >> 5;
    int row0 = blockIdx.x * 64;
    int rb = ty * 8, cb = tx * 4;

    float acc[8][4];
#pragma unroll
    for (int i = 0; i < 8; i++)
#pragma unroll
        for (int j = 0; j < 4; j++) acc[i][j] = 0.f;

    for (int k0 = 0; k0 < K; k0 += BK) {
        for (int i = tid; i < BK * 32; i += 256) {
            int k = i >> 5, c = (i & 31) * 4;
            *(float4*)&Ws[k][c] = *(const float4*)&W[(k0 + k) * HID + c];
        }
        for (int i = tid; i < 64 * (BK / 4); i += 256) {
            int r = i / (BK / 4), k4 = (i % (BK / 4)) * 4;
            int g = row0 + r;
            float4 v = make_float4(0.f, 0.f, 0.f, 0.f);
            if (g < NN) v = *(const float4*)&X[(size_t)g * K + k0 + k4];
            if (NORM) {
                float4 a = __ldg((const float4*)ab + (k0 + k4) / 4);
                float4 b = __ldg((const float4*)(ab + HID) + (k0 + k4) / 4);
                v.x = leaky(v.x * a.x + b.x);
                v.y = leaky(v.y * a.y + b.y);
                v.z = leaky(v.z * a.z + b.z);
                v.w = leaky(v.w * a.w + b.w);
            }
            *(float4*)&Xs[r][k4] = v;
        }
        __syncthreads();

#pragma unroll
        for (int k = 0; k < BK; k += 4) {
            float xv[8][4];
#pragma unroll
            for (int i = 0; i < 8; i++)
                *(float4*)xv[i] = *(const float4*)&Xs[rb + i][k];
#pragma unroll
            for (int kk = 0; kk < 4; kk++) {
                float4 w = *(const float4*)&Ws[k + kk][cb];
#pragma unroll
                for (int i = 0; i < 8; i++) {
                    float x = xv[i][kk];
                    acc[i][0] += x * w.x;
                    acc[i][1] += x * w.y;
                    acc[i][2] += x * w.z;
                    acc[i][3] += x * w.w;
                }
            }
        }
        __syncthreads();
    }

#pragma unroll
    for (int i = 0; i < 8; i++) {
        int g = row0 + rb + i;
        if (g < NN) {
            float c = __ldg(&cs[g]);
            *(float4*)&out[(size_t)g * HID + cb] =
                make_float4(acc[i][0] * c, acc[i][1] * c, acc[i][2] * c, acc[i][3] * c);
        }
    }
}

// ---------------------------------------------------------------------------
// Fused aggregation: warp per dst node.
//   acc = sum over in-edges of hs[src] ; y = acc*cd ; column sum/sumsq stats.
// No atomics on node data; stats reduced through shared then one global
// atomicAdd per channel per block.
// ---------------------------------------------------------------------------
__global__ void __launch_bounds__(256)
k_aggstats(const float* __restrict__ hs, const int* __restrict__ csr_start,
           const int* __restrict__ csr_src, const float* __restrict__ cd,
           float* __restrict__ y, float* __restrict__ stats) {
    __shared__ float s_sum[8][HID];
    __shared__ float s_sq [8][HID];

    int warp = threadIdx.x >> 5, lane = threadIdx.x & 31;
    int d = blockIdx.x * 8 + warp;

    float4 acc = make_float4(0.f, 0.f, 0.f, 0.f);
    if (d < NN) {
        int start = __ldg(&csr_start[d]);
        int end   = __ldg(&csr_start[d + 1]);
        for (int i = start; i < end; i += 32) {
            int s = (i + lane < end) ? __ldg(&csr_src[i + lane]) : 0;
            int cnt = min(32, end - i);
            for (int j = 0; j < cnt; j++) {
                int sj = __shfl_sync(0xffffffffu, s, j);
                float4 v = __ldg((const float4*)(hs + (size_t)sj * HID) + lane);
                acc.x += v.x; acc.y += v.y; acc.z += v.z; acc.w += v.w;
            }
        }
        float c = __ldg(&cd[d]);
        acc.x *= c; acc.y *= c; acc.z *= c; acc.w *= c;
        *((float4*)(y + (size_t)d * HID) + lane) = acc;
    }

    // stats: per-warp partials in shared, then cross-warp sum, one atomic each
    int c0 = lane * 4;
    s_sum[warp][c0]     = acc.x; s_sum[warp][c0 + 1] = acc.y;
    s_sum[warp][c0 + 2] = acc.z; s_sum[warp][c0 + 3] = acc.w;
    s_sq [warp][c0]     = acc.x * acc.x; s_sq [warp][c0 + 1] = acc.y * acc.y;
    s_sq [warp][c0 + 2] = acc.z * acc.z; s_sq [warp][c0 + 3] = acc.w * acc.w;
    __syncthreads();

    int t = threadIdx.x;
    if (t < HID) {
        float s = 0.f;
#pragma unroll
        for (int w = 0; w < 8; w++) s += s_sum[w][t];
        atomicAdd(&stats[t], s);
    } else {
        int c = t - HID;
        float s = 0.f;
#pragma unroll
        for (int w = 0; w < 8; w++) s += s_sq[w][c];
        atomicAdd(&stats[HID + c], s);
    }
}

// ---------------------------------------------------------------------------
// Per-channel alpha/beta: norm(y) = y*alpha + beta
// var = E[y^2] - m^2 (2s - s^2)
// ---------------------------------------------------------------------------
__global__ void k_alpha_beta(const float* __restrict__ stats,
                             const float* __restrict__ gw, const float* __restrict__ gb,
                             const float* __restrict__ gs, float* __restrict__ ab) {
    int c = threadIdx.x;
    float m   = stats[c] * (1.f / (float)NN);
    float ex2 = stats[HID + c] * (1.f / (float)NN);
    float s   = gs[c];
    float var = ex2 - m * m * (2.f * s - s * s);
    float inv = rsqrtf(var + EPS);
    float a   = inv * gw[c];
    ab[c]       = a;
    ab[HID + c] = gb[c] - s * m * a;
}

// ---------------------------------------------------------------------------
// Readout: block per graph, thread per channel, norm+leaky on the fly
// ---------------------------------------------------------------------------
__global__ void k_readout(const float* __restrict__ y, const float* __restrict__ ab,
                          const int* __restrict__ gstart,
                          float* __restrict__ out, int layer) {
    int g = blockIdx.x;
    int c = threadIdx.x;
    int s0 = gstart[g], s1 = gstart[g + 1];
    float a = __ldg(&ab[c]);
    float b = __ldg(&ab[HID + c]);
    float sum = 0.f, mx = -CUDART_INF_F, mn = CUDART_INF_F;
    for (int r = s0; r < s1; r++) {
        float v = leaky(__ldg(&y[(size_t)r * HID + c]) * a + b);
        sum += v;
        mx = fmaxf(mx, v);
        mn = fminf(mn, v);
    }
    int cnt = s1 - s0;
    float mean = sum / fmaxf((float)cnt, 1.f);
    if (cnt == 0) { mx = 0.f; mn = 0.f; }
    float* o = out + (size_t)g * (9 * HID) + layer * (3 * HID);
    o[c]           = leaky(mean);
    o[HID + c]     = leaky(mx);
    o[2 * HID + c] = leaky(mn);
}

// ---------------------------------------------------------------------------
// Launch
// ---------------------------------------------------------------------------
extern "C" void kernel_launch(void* const* d_in, const int* in_sizes, int n_in,
                              void* d_out, int out_size) {
    const float* X   = (const float*)d_in[0];
    const float* W1  = (const float*)d_in[1];
    const float* W2  = (const float*)d_in[2];
    const float* W3  = (const float*)d_in[3];
    const float* gw  = (const float*)d_in[4];
    const float* gb  = (const float*)d_in[5];
    const float* gs  = (const float*)d_in[6];
    const int*   src = (const int*)d_in[7];
    const int*   dst = (const int*)d_in[8];
    const int*   gid = (const int*)d_in[9];
    float* out = (float*)d_out;

    float *hs, *y, *cs, *cd, *stats, *ab;
    int *deg, *gstart, *csr_start, *cursor, *csr_src, *bsum;
    cudaGetSymbolAddress((void**)&hs,        g_hs);
    cudaGetSymbolAddress((void**)&y,         g_y);
    cudaGetSymbolAddress((void**)&cs,        g_cs);
    cudaGetSymbolAddress((void**)&cd,        g_cd);
    cudaGetSymbolAddress((void**)&stats,     g_stats);
    cudaGetSymbolAddress((void**)&ab,        g_ab);
    cudaGetSymbolAddress((void**)&deg,       g_deg);
    cudaGetSymbolAddress((void**)&gstart,    g_gstart);
    cudaGetSymbolAddress((void**)&csr_start, g_csr_start);
    cudaGetSymbolAddress((void**)&cursor,    g_cursor);
    cudaGetSymbolAddress((void**)&csr_src,   g_csr_src);
    cudaGetSymbolAddress((void**)&bsum,      g_bsum);

    // --- setup: degrees, segment starts, dst-CSR ---
    k_setup_zero<<<256, 256>>>(deg, stats);
    k_degrees<<<(EE + 255) / 256, 256>>>(src, dst, deg);
    k_invdeg<<<(NN + 255) / 256, 256>>>(deg, cs, cd);
    k_gstart<<<(NN + 255) / 256, 256>>>(gid, gstart);
    k_scan1<<<NB_SCAN, 256>>>(deg + NN, bsum);
    k_scan2<<<1, 256>>>(bsum);
    k_scan3<<<NB_SCAN, 256>>>(deg + NN, bsum, csr_start, cursor);
    k_fill_csr<<<(EE + 255) / 256, 256>>>(src, dst, cursor, csr_src);

    const float* Wl[3] = {W1, W2, W3};
    const int gemm_grid = (NN + 63) / 64;
    const int agg_grid = (NN + 7) / 8;

    for (int L = 0; L < 3; L++) {
        if (L == 0)
            k_gemm_cs<INF_, false><<<gemm_grid, 256>>>(X, Wl[0], cs, nullptr, hs);
        else
            k_gemm_cs<HID, true><<<gemm_grid, 256>>>(y, Wl[L], cs,
                                                     ab + (L - 1) * 2 * HID, hs);

        k_aggstats<<<agg_grid, 256>>>(hs, csr_start, csr_src, cd, y,
                                      stats + L * 2 * HID);

        k_alpha_beta<<<1, HID>>>(stats + L * 2 * HID, gw + L * HID, gb + L * HID,
                                 gs + L * HID, ab + L * 2 * HID);

        k_readout<<<GG, HID>>>(y, ab + L * 2 * HID, gstart, out, L);
    }
}

// round 5
// speedup vs baseline: 2.2806x; 1.0512x over previous
#include <cuda_runtime.h>
#include <cuda_fp16.h>
#include <math_constants.h>
#include <cstdint>

// Problem constants (fixed by the dataset)
#define NN   50000
#define EE   600000
#define GG   1000
#define HID  128
#define INF_ 64
#define EPS  1e-5f
#define SLOPE 0.01f

#define NB_SCAN ((NN + 255) / 256)

// ---------------------------------------------------------------------------
// Scratch (static __device__ arrays; no allocation anywhere)
// ---------------------------------------------------------------------------
__device__ __half g_hs [NN * HID];    // (x@W)*cs in fp16, gather source
__device__ float  g_y  [NN * HID];    // y = sum_in * cd (pre-norm layer output)
__device__ float  g_cs [NN];
__device__ float  g_cd [NN];
__device__ int    g_deg[2 * NN];
__device__ int    g_csr_start[NN + 1];
__device__ int    g_cursor[NN];
__device__ int    g_csr_src[EE];
__device__ int    g_bsum[256];
__device__ float  g_stats[3 * 2 * HID];
__device__ int    g_gstart[GG + 1];

__device__ __forceinline__ float leaky(float v) { return v > 0.f ? v : SLOPE * v; }

// alpha/beta for channel c from this layer's stats + gn params
__device__ __forceinline__ void alpha_beta(const float* __restrict__ stats,
                                           const float* __restrict__ gw,
                                           const float* __restrict__ gb,
                                           const float* __restrict__ gs,
                                           int c, float& a, float& b) {
    float m   = stats[c] * (1.f / (float)NN);
    float ex2 = stats[HID + c] * (1.f / (float)NN);
    float s   = gs[c];
    float var = ex2 - m * m * (2.f * s - s * s);
    float inv = rsqrtf(var + EPS);
    a = inv * gw[c];
    b = gb[c] - s * m * a;
}

// ---------------------------------------------------------------------------
// Setup zero: deg + stats
// ---------------------------------------------------------------------------
__global__ void k_setup_zero(int* __restrict__ deg, float* __restrict__ stats) {
    int i = blockIdx.x * blockDim.x + threadIdx.x;
    int stride = gridDim.x * blockDim.x;
    for (int j = i; j < 2 * NN; j += stride) deg[j] = 0;
    for (int j = i; j < 3 * 2 * HID; j += stride) stats[j] = 0.f;
}

// ---------------------------------------------------------------------------
// Degrees
// ---------------------------------------------------------------------------
__global__ void k_degrees(const int* __restrict__ src, const int* __restrict__ dst,
                          int* __restrict__ deg) {
    int e = blockIdx.x * blockDim.x + threadIdx.x;
    if (e >= EE) return;
    atomicAdd(&deg[src[e]], 1);
    atomicAdd(&deg[NN + dst[e]], 1);
}

__global__ void k_invdeg(const int* __restrict__ deg,
                         float* __restrict__ cs, float* __restrict__ cd) {
    int i = blockIdx.x * blockDim.x + threadIdx.x;
    if (i >= NN) return;
    cs[i] = rsqrtf(fmaxf((float)deg[i], 1.f));
    cd[i] = rsqrtf(fmaxf((float)deg[NN + i], 1.f));
}

// ---------------------------------------------------------------------------
// Graph segment starts (graph_ids sorted ascending)
// ---------------------------------------------------------------------------
__global__ void k_gstart(const int* __restrict__ gid, int* __restrict__ gstart) {
    int i = blockIdx.x * blockDim.x + threadIdx.x;
    if (i >= NN) return;
    int g  = gid[i];
    int gp = (i == 0) ? -1 : gid[i - 1];
    for (int gg = gp + 1; gg <= g; gg++) gstart[gg] = i;
    if (i == NN - 1)
        for (int gg = g + 1; gg <= GG; gg++) gstart[gg] = NN;
}

// ---------------------------------------------------------------------------
// CSR-by-dst build (3-step scan + fill)
// ---------------------------------------------------------------------------
__global__ void k_scan1(const int* __restrict__ indeg, int* __restrict__ bsum) {
    __shared__ int sh[256];
    int i = blockIdx.x * 256 + threadIdx.x;
    sh[threadIdx.x] = (i < NN) ? indeg[i] : 0;
    __syncthreads();
    for (int o = 128; o > 0; o >>= 1) {
        if (threadIdx.x < o) sh[threadIdx.x] += sh[threadIdx.x + o];
        __syncthreads();
    }
    if (threadIdx.x == 0) bsum[blockIdx.x] = sh[0];
}

__global__ void k_scan2(int* __restrict__ bsum) {
    __shared__ int sh[256];
    int tid = threadIdx.x;
    int v = (tid < NB_SCAN) ? bsum[tid] : 0;
    sh[tid] = v;
    __syncthreads();
    for (int o = 1; o < 256; o <<= 1) {
        int t = (tid >= o) ? sh[tid - o] : 0;
        __syncthreads();
        sh[tid] += t;
        __syncthreads();
    }
    if (tid < NB_SCAN) bsum[tid] = sh[tid] - v;
}

__global__ void k_scan3(const int* __restrict__ indeg, const int* __restrict__ bsum,
                        int* __restrict__ csr_start, int* __restrict__ cursor) {
    __shared__ int sh[256];
    int tid = threadIdx.x;
    int i = blockIdx.x * 256 + tid;
    int v = (i < NN) ? indeg[i] : 0;
    sh[tid] = v;
    __syncthreads();
    for (int o = 1; o < 256; o <<= 1) {
        int t = (tid >= o) ? sh[tid - o] : 0;
        __syncthreads();
        sh[tid] += t;
        __syncthreads();
    }
    int excl = sh[tid] - v + bsum[blockIdx.x];
    if (i < NN) { csr_start[i] = excl; cursor[i] = excl; }
    if (i == NN - 1) csr_start[NN] = excl + v;
}

__global__ void k_fill_csr(const int* __restrict__ src, const int* __restrict__ dst,
                           int* __restrict__ cursor, int* __restrict__ csr_src) {
    int e = blockIdx.x * blockDim.x + threadIdx.x;
    if (e >= EE) return;
    int pos = atomicAdd(&cursor[dst[e]], 1);
    csr_src[pos] = src[e];
}

// ---------------------------------------------------------------------------
// FFMA GEMM: hs[N,128] = (f(X)[N,K] @ W[K,128]) * cs[row], output fp16.
// If NORM: f(x) = leaky(x*alpha[c]+beta[c]); alpha/beta computed per block
// from the previous layer's stats (no separate kernel, no ab buffer).
// Block: 64 rows x 128 cols, 256 threads, 8x4 micro-tile, BK=32.
// ---------------------------------------------------------------------------
template <int K, bool NORM>
__global__ void __launch_bounds__(256, 2)
k_gemm_cs(const float* __restrict__ X, const float* __restrict__ W,
          const float* __restrict__ cs,
          const float* __restrict__ stats, const float* __restrict__ gw,
          const float* __restrict__ gb, const float* __restrict__ gs,
          __half* __restrict__ out) {
    constexpr int BK = 32;
    __shared__ float Ws[BK][HID];
    __shared__ float Xs[64][BK];
    __shared__ float s_a[HID], s_b[HID];

    int tid = threadIdx.x;
    int tx = tid & 31, ty = tid >> 5;
    int row0 = blockIdx.x * 64;
    int rb = ty * 8, cb = tx * 4;

    if (NORM) {
        if (tid < HID) {
            float a, b;
            alpha_beta(stats, gw, gb, gs, tid, a, b);
            s_a[tid] = a;
            s_b[tid] = b;
        }
        __syncthreads();
    }

    float acc[8][4];
#pragma unroll
    for (int i = 0; i < 8; i++)
#pragma unroll
        for (int j = 0; j < 4; j++) acc[i][j] = 0.f;

    for (int k0 = 0; k0 < K; k0 += BK) {
        for (int i = tid; i < BK * 32; i += 256) {
            int k = i >> 5, c = (i & 31) * 4;
            *(float4*)&Ws[k][c] = *(const float4*)&W[(k0 + k) * HID + c];
        }
        for (int i = tid; i < 64 * (BK / 4); i += 256) {
            int r = i / (BK / 4), k4 = (i % (BK / 4)) * 4;
            int g = row0 + r;
            float4 v = make_float4(0.f, 0.f, 0.f, 0.f);
            if (g < NN) v = *(const float4*)&X[(size_t)g * K + k0 + k4];
            if (NORM) {
                float4 a = *(const float4*)&s_a[k0 + k4];
                float4 b = *(const float4*)&s_b[k0 + k4];
                v.x = leaky(v.x * a.x + b.x);
                v.y = leaky(v.y * a.y + b.y);
                v.z = leaky(v.z * a.z + b.z);
                v.w = leaky(v.w * a.w + b.w);
            }
            *(float4*)&Xs[r][k4] = v;
        }
        __syncthreads();

#pragma unroll
        for (int k = 0; k < BK; k += 4) {
            float xv[8][4];
#pragma unroll
            for (int i = 0; i < 8; i++)
                *(float4*)xv[i] = *(const float4*)&Xs[rb + i][k];
#pragma unroll
            for (int kk = 0; kk < 4; kk++) {
                float4 w = *(const float4*)&Ws[k + kk][cb];
#pragma unroll
                for (int i = 0; i < 8; i++) {
                    float x = xv[i][kk];
                    acc[i][0] += x * w.x;
                    acc[i][1] += x * w.y;
                    acc[i][2] += x * w.z;
                    acc[i][3] += x * w.w;
                }
            }
        }
        __syncthreads();
    }

#pragma unroll
    for (int i = 0; i < 8; i++) {
        int g = row0 + rb + i;
        if (g < NN) {
            float c = __ldg(&cs[g]);
            __half2 p0 = __floats2half2_rn(acc[i][0] * c, acc[i][1] * c);
            __half2 p1 = __floats2half2_rn(acc[i][2] * c, acc[i][3] * c);
            uint2 u;
            u.x = *reinterpret_cast<uint32_t*>(&p0);
            u.y = *reinterpret_cast<uint32_t*>(&p1);
            *(uint2*)&out[(size_t)g * HID + cb] = u;
        }
    }
}

// ---------------------------------------------------------------------------
// Fused aggregation (fp16 source): warp per dst node.
// 16 lanes cover one 256B row (uint4 = 8 halves each); two half-lane groups
// x 2-deep unroll = 4 edges in flight per warp. fp32 accumulation,
// shfl_xor(16) combine, y = acc*cd, column stats via shared reduction.
// ---------------------------------------------------------------------------
__global__ void __launch_bounds__(256)
k_aggstats(const __half* __restrict__ hs, const int* __restrict__ csr_start,
           const int* __restrict__ csr_src, const float* __restrict__ cd,
           float* __restrict__ y, float* __restrict__ stats) {
    __shared__ float s_sum[8][HID];
    __shared__ float s_sq [8][HID];

    int warp = threadIdx.x >> 5, lane = threadIdx.x & 31;
    int lg = lane >> 4, li = lane & 15;
    int d = blockIdx.x * 8 + warp;

    float2 acc[4];
#pragma unroll
    for (int j = 0; j < 4; j++) acc[j] = make_float2(0.f, 0.f);

    if (d < NN) {
        int start = __ldg(&csr_start[d]);
        int end   = __ldg(&csr_start[d + 1]);
        for (int i = start; i < end; i += 4) {
            int e0 = i + lg;
            int e1 = i + lg + 2;
            if (e0 < end) {
                int s = __ldg(&csr_src[e0]);
                uint4 u = __ldg((const uint4*)(hs + (size_t)s * HID) + li);
                float2 f;
                f = __half22float2(*reinterpret_cast<__half2*>(&u.x));
                acc[0].x += f.x; acc[0].y += f.y;
                f = __half22float2(*reinterpret_cast<__half2*>(&u.y));
                acc[1].x += f.x; acc[1].y += f.y;
                f = __half22float2(*reinterpret_cast<__half2*>(&u.z));
                acc[2].x += f.x; acc[2].y += f.y;
                f = __half22float2(*reinterpret_cast<__half2*>(&u.w));
                acc[3].x += f.x; acc[3].y += f.y;
            }
            if (e1 < end) {
                int s = __ldg(&csr_src[e1]);
                uint4 u = __ldg((const uint4*)(hs + (size_t)s * HID) + li);
                float2 f;
                f = __half22float2(*reinterpret_cast<__half2*>(&u.x));
                acc[0].x += f.x; acc[0].y += f.y;
                f = __half22float2(*reinterpret_cast<__half2*>(&u.y));
                acc[1].x += f.x; acc[1].y += f.y;
                f = __half22float2(*reinterpret_cast<__half2*>(&u.z));
                acc[2].x += f.x; acc[2].y += f.y;
                f = __half22float2(*reinterpret_cast<__half2*>(&u.w));
                acc[3].x += f.x; acc[3].y += f.y;
            }
        }
        // combine the two half-lane groups (same channels, different edges)
#pragma unroll
        for (int j = 0; j < 4; j++) {
            acc[j].x += __shfl_xor_sync(0xffffffffu, acc[j].x, 16);
            acc[j].y += __shfl_xor_sync(0xffffffffu, acc[j].y, 16);
        }
        float c = __ldg(&cd[d]);
#pragma unroll
        for (int j = 0; j < 4; j++) { acc[j].x *= c; acc[j].y *= c; }
        if (lg == 0) {
            float4 o0 = make_float4(acc[0].x, acc[0].y, acc[1].x, acc[1].y);
            float4 o1 = make_float4(acc[2].x, acc[2].y, acc[3].x, acc[3].y);
            *(float4*)(y + (size_t)d * HID + li * 8)     = o0;
            *(float4*)(y + (size_t)d * HID + li * 8 + 4) = o1;
        }
    }

    if (lg == 0) {
#pragma unroll
        for (int j = 0; j < 4; j++) {
            int c0 = li * 8 + 2 * j;
            float vx = (d < NN) ? acc[j].x : 0.f;
            float vy = (d < NN) ? acc[j].y : 0.f;
            s_sum[warp][c0]     = vx;
            s_sum[warp][c0 + 1] = vy;
            s_sq [warp][c0]     = vx * vx;
            s_sq [warp][c0 + 1] = vy * vy;
        }
    }
    __syncthreads();

    int t = threadIdx.x;
    if (t < HID) {
        float s = 0.f;
#pragma unroll
        for (int w = 0; w < 8; w++) s += s_sum[w][t];
        atomicAdd(&stats[t], s);
    } else {
        int c = t - HID;
        float s = 0.f;
#pragma unroll
        for (int w = 0; w < 8; w++) s += s_sq[w][c];
        atomicAdd(&stats[HID + c], s);
    }
}

// ---------------------------------------------------------------------------
// Readout: block per graph, thread per channel; alpha/beta computed per
// thread from stats, norm+leaky applied on the fly.
// ---------------------------------------------------------------------------
__global__ void k_readout(const float* __restrict__ y,
                          const float* __restrict__ stats,
                          const float* __restrict__ gw, const float* __restrict__ gb,
                          const float* __restrict__ gs,
                          const int* __restrict__ gstart,
                          float* __restrict__ out, int layer) {
    int g = blockIdx.x;
    int c = threadIdx.x;
    float a, b;
    alpha_beta(stats, gw, gb, gs, c, a, b);
    int s0 = gstart[g], s1 = gstart[g + 1];
    float sum = 0.f, mx = -CUDART_INF_F, mn = CUDART_INF_F;
    for (int r = s0; r < s1; r++) {
        float v = leaky(__ldg(&y[(size_t)r * HID + c]) * a + b);
        sum += v;
        mx = fmaxf(mx, v);
        mn = fminf(mn, v);
    }
    int cnt = s1 - s0;
    float mean = sum / fmaxf((float)cnt, 1.f);
    if (cnt == 0) { mx = 0.f; mn = 0.f; }
    float* o = out + (size_t)g * (9 * HID) + layer * (3 * HID);
    o[c]           = leaky(mean);
    o[HID + c]     = leaky(mx);
    o[2 * HID + c] = leaky(mn);
}

// ---------------------------------------------------------------------------
// Launch
// ---------------------------------------------------------------------------
extern "C" void kernel_launch(void* const* d_in, const int* in_sizes, int n_in,
                              void* d_out, int out_size) {
    const float* X   = (const float*)d_in[0];
    const float* W1  = (const float*)d_in[1];
    const float* W2  = (const float*)d_in[2];
    const float* W3  = (const float*)d_in[3];
    const float* gw  = (const float*)d_in[4];
    const float* gb  = (const float*)d_in[5];
    const float* gs  = (const float*)d_in[6];
    const int*   src = (const int*)d_in[7];
    const int*   dst = (const int*)d_in[8];
    const int*   gid = (const int*)d_in[9];
    float* out = (float*)d_out;

    __half* hs;
    float *y, *cs, *cd, *stats;
    int *deg, *gstart, *csr_start, *cursor, *csr_src, *bsum;
    cudaGetSymbolAddress((void**)&hs,        g_hs);
    cudaGetSymbolAddress((void**)&y,         g_y);
    cudaGetSymbolAddress((void**)&cs,        g_cs);
    cudaGetSymbolAddress((void**)&cd,        g_cd);
    cudaGetSymbolAddress((void**)&stats,     g_stats);
    cudaGetSymbolAddress((void**)&deg,       g_deg);
    cudaGetSymbolAddress((void**)&gstart,    g_gstart);
    cudaGetSymbolAddress((void**)&csr_start, g_csr_start);
    cudaGetSymbolAddress((void**)&cursor,    g_cursor);
    cudaGetSymbolAddress((void**)&csr_src,   g_csr_src);
    cudaGetSymbolAddress((void**)&bsum,      g_bsum);

    // --- setup: degrees, segment starts, dst-CSR ---
    k_setup_zero<<<256, 256>>>(deg, stats);
    k_degrees<<<(EE + 255) / 256, 256>>>(src, dst, deg);
    k_invdeg<<<(NN + 255) / 256, 256>>>(deg, cs, cd);
    k_gstart<<<(NN + 255) / 256, 256>>>(gid, gstart);
    k_scan1<<<NB_SCAN, 256>>>(deg + NN, bsum);
    k_scan2<<<1, 256>>>(bsum);
    k_scan3<<<NB_SCAN, 256>>>(deg + NN, bsum, csr_start, cursor);
    k_fill_csr<<<(EE + 255) / 256, 256>>>(src, dst, cursor, csr_src);

    const float* Wl[3] = {W1, W2, W3};
    const int gemm_grid = (NN + 63) / 64;
    const int agg_grid = (NN + 7) / 8;

    for (int L = 0; L < 3; L++) {
        if (L == 0)
            k_gemm_cs<INF_, false><<<gemm_grid, 256>>>(
                X, Wl[0], cs, nullptr, nullptr, nullptr, nullptr, hs);
        else
            k_gemm_cs<HID, true><<<gemm_grid, 256>>>(
                y, Wl[L], cs, stats + (L - 1) * 2 * HID,
                gw + (L - 1) * HID, gb + (L - 1) * HID, gs + (L - 1) * HID, hs);

        k_aggstats<<<agg_grid, 256>>>(hs, csr_start, csr_src, cd, y,
                                      stats + L * 2 * HID);

        k_readout<<<GG, HID>>>(y, stats + L * 2 * HID, gw + L * HID,
                               gb + L * HID, gs + L * HID, gstart, out, L);
    }
}